// round 11
// baseline (speedup 1.0000x reference)
#include <cuda_runtime.h>

#define EXTENT 7
#define NBOX   1024
#define CH     256
#define NSAMP  (EXTENT * EXTENT)
#define NTASK  (NBOX * NSAMP)        // 50176
#define CVEC   (CH / 4)              // 64 float4 per pixel
#define TPB    16                    // tasks per CTA

__device__ __forceinline__ void stcs4(float4* p, float4 v) {
    asm volatile("st.global.cs.v4.f32 [%0], {%1,%2,%3,%4};"
                 :: "l"(p), "f"(v.x), "f"(v.y), "f"(v.z), "f"(v.w) : "memory");
}

struct Corners { float4 a, b, c, d; };

__device__ __forceinline__ Corners load_corners(
    const int4 d, int tx,
    const float* p2, const float* p3, const float* p4, const float* p5)
{
    const int lvl  = d.y & 3;
    const int wrow = d.y & ~3;
    const float* f = (lvl == 0) ? p2 : (lvl == 1) ? p3 : (lvl == 2) ? p4 : p5;
    const float4* f4 = (const float4*)f;
    const int b = d.x + tx;
    Corners c;
    c.a = f4[b];
    c.b = f4[b + CVEC];
    c.c = f4[b + wrow];
    c.d = f4[b + wrow + CVEC];
    return c;
}

__device__ __forceinline__ float4 bilerp(const Corners& c, const int4 d)
{
    const float wy = __int_as_float(d.z);
    const float wx = __int_as_float(d.w);
    const float w00 = (1.0f - wy) * (1.0f - wx);
    const float w01 = (1.0f - wy) * wx;
    const float w10 = wy * (1.0f - wx);
    const float w11 = wy * wx;
    float4 r;
    r.x = c.a.x * w00 + c.b.x * w01 + c.c.x * w10 + c.d.x * w11;
    r.y = c.a.y * w00 + c.b.y * w01 + c.c.y * w10 + c.d.y * w11;
    r.z = c.a.z * w00 + c.b.z * w01 + c.c.z * w10 + c.d.z * w11;
    r.w = c.a.w * w00 + c.b.w * w01 + c.c.w * w10 + c.d.w * w11;
    return r;
}

// 3136 CTAs x 256 threads. Threads 0-15 build 16 task descriptors in smem;
// then each 64-thread group (ty) gathers 4 consecutive tasks, pipelined.
__global__ __launch_bounds__(256)
void roi_align_fused_kernel(
    const float* __restrict__ metadata,
    const float* __restrict__ boxes,
    const float* __restrict__ p2,
    const float* __restrict__ p3,
    const float* __restrict__ p4,
    const float* __restrict__ p5,
    float* __restrict__ out)
{
    __shared__ int4 desc[TPB];

    const int tid   = threadIdx.x;
    const int tbase = blockIdx.x * TPB;

    if (tid < TPB) {
        const int t   = tbase + tid;
        const int box = t / NSAMP;
        const int s   = t - box * NSAMP;
        const int gy  = s / EXTENT;
        const int gx  = s - gy * EXTENT;

        const float rows = metadata[0];
        const float cols = metadata[1];
        const float4 bx = ((const float4*)boxes)[box];    // x1,y1,x2,y2

        const float h = bx.w - bx.y;
        const float w = bx.z - bx.x;

        // roi_level = min(5, max(2, 4 + round(log2(sqrt(h*w)/sqrt(rows*cols)))))
        // rintf = round-half-to-even, matching jnp.round.
        const float roi  = logf(sqrtf(h * w) / sqrtf(rows * cols)) * (1.0f / logf(2.0f));
        const float lvlf = fminf(5.0f, fmaxf(2.0f, 4.0f + rintf(roi)));
        const int   lvl  = (int)lvlf - 2;                 // 0..3
        const int   H    = 256 >> lvl;

        const float gyf = (float)gy / (float)(EXTENT - 1);
        const float gxf = (float)gx / (float)(EXTENT - 1);
        const float ny1 = bx.y / (rows - 1.0f);
        const float ny2 = bx.w / (rows - 1.0f);
        const float nx1 = bx.x / (cols - 1.0f);
        const float nx2 = bx.z / (cols - 1.0f);
        const float ysv = (ny1 + (ny2 - ny1) * gyf) * (float)(H - 1);
        const float xsv = (nx1 + (nx2 - nx1) * gxf) * (float)(H - 1);
        const float y0f = fminf(fmaxf(floorf(ysv), 0.0f), (float)(H - 2));
        const float x0f = fminf(fmaxf(floorf(xsv), 0.0f), (float)(H - 2));

        const int off  = ((int)y0f * H + (int)x0f) * CVEC;
        const int pack = (H * CVEC) | lvl;                // row stride has low bits 0

        desc[tid] = make_int4(off, pack,
                              __float_as_int(ysv - y0f),
                              __float_as_int(xsv - x0f));
    }
    __syncthreads();

    const int tx = tid & 63;
    const int ty = tid >> 6;
    const int base = tbase + ty * 4;        // 4 consecutive tasks per group

    const int4 d0 = desc[ty * 4 + 0];
    const int4 d1 = desc[ty * 4 + 1];
    const int4 d2 = desc[ty * 4 + 2];
    const int4 d3 = desc[ty * 4 + 3];

    float4* __restrict__ o4 = (float4*)out;

    // Software pipeline: ~12 loads in flight before first consume.
    Corners c0 = load_corners(d0, tx, p2, p3, p4, p5);
    Corners c1 = load_corners(d1, tx, p2, p3, p4, p5);
    Corners c2 = load_corners(d2, tx, p2, p3, p4, p5);

    float4 r0 = bilerp(c0, d0);
    stcs4(&o4[(base + 0) * CVEC + tx], r0);

    Corners c3 = load_corners(d3, tx, p2, p3, p4, p5);

    float4 r1 = bilerp(c1, d1);
    stcs4(&o4[(base + 1) * CVEC + tx], r1);
    float4 r2 = bilerp(c2, d2);
    stcs4(&o4[(base + 2) * CVEC + tx], r2);
    float4 r3 = bilerp(c3, d3);
    stcs4(&o4[(base + 3) * CVEC + tx], r3);
}

extern "C" void kernel_launch(void* const* d_in, const int* in_sizes, int n_in,
                              void* d_out, int out_size) {
    const float* metadata = (const float*)d_in[0];
    const float* boxes    = (const float*)d_in[1];
    const float* p2       = (const float*)d_in[2];
    const float* p3       = (const float*)d_in[3];
    const float* p4       = (const float*)d_in[4];
    const float* p5       = (const float*)d_in[5];
    float* out = (float*)d_out;

    roi_align_fused_kernel<<<NTASK / TPB, 256>>>(metadata, boxes, p2, p3, p4, p5, out);
}